// round 15
// baseline (speedup 1.0000x reference)
#include <cuda_runtime.h>
#include <math.h>

#define NHIT 80000
#define KOBJ 512
// k_hits geometry (balanced, from R14)
#define HGRID 296
#define HTHR  256
#define HNT   (HGRID * HTHR)        // 75776
#define HNEXTRA (NHIT - HNT)        // 4224 = 132 chunks
#define HWSTRIDE 18
// k_rep geometry: 148 blocks x 256 thr, 2 hits/thread
#define RGRID 148
#define RTHR  256
#define RNT   (RGRID * RTHR)        // 37888 threads
#define RBASE (2 * RNT)             // 75776 base hits
#define RNEXTRA (NHIT - RBASE)      // 4224 = 132 chunks
#define RWSTRIDE 9                  // 1184 warps / 132 chunks
#define EPSF 1e-9f

// ---------------- scratch (device globals; zero at load, reset after use) ----------
__device__ float4 g_hit[NHIT];                 // x, y, q, t_idx (int bits)
__device__ float4 g_A[KOBJ];                   // -2ax, -2ay, |a|^2+1e-6, wrep
__device__ float  g_watt[KOBJ];                // q_a/(cnt+eps)
__device__ float  g_beta_a[KOBJ];
__device__ unsigned long long g_amax[KOBJ];    // packed (beta_bits<<32 | ~idx)
__device__ int    g_cnt[KOBJ];
__device__ float2 g_numden[KOBJ];              // payload num, den
__device__ float  g_pairsum, g_noise_sum, g_noise_cnt, g_cc_sum;
__device__ unsigned g_done_h, g_done_p;

__device__ __forceinline__ float clampb(float b) {
    return fminf(fmaxf(b, 1e-6f), 1.0f - 1e-6f);
}
__device__ __forceinline__ float softclip_f(float x, float c) {
    x = x * (1.0f / c);
    if (x > 1.0f) x = __logf(x + 1.0f);
    return x * c;
}
__device__ __forceinline__ float huber_f(float x, float d) {
    float ax = fabsf(x);
    return ax < d ? x * x : d * d + 2.0f * d * (ax - d);
}
__device__ __forceinline__ float sqapx(float x) {
    float s; asm("sqrt.approx.f32 %0, %1;" : "=f"(s) : "f"(x)); return s;
}

// ---------------- phase A body: one hit ----------------
__device__ __forceinline__ void process_hit(int i,
        const float* __restrict__ pb,  const float* __restrict__ cc,
        const float* __restrict__ pe,  const float* __restrict__ pp,
        const float* __restrict__ pt,  const float* __restrict__ pid,
        const int*   __restrict__ tix, const float* __restrict__ te,
        const float* __restrict__ tp,  const float* __restrict__ tt,
        float& ns, float& ncnt, float& ccs) {
    float  braw = pb[i];
    int    t    = tix[i];
    float2 ccv  = ((const float2*)cc)[i];
    float  pev  = pe[i];
    float2 ppv  = ((const float2*)pp)[i];
    float  ptv  = pt[i];
    float  tev  = te[i];
    float2 tpv  = ((const float2*)tp)[i];
    float  ttv  = tt[i];
    float2 pid0 = ((const float2*)pid)[3 * i];
    float2 pid1 = ((const float2*)pid)[3 * i + 1];
    float2 pid2 = ((const float2*)pid)[3 * i + 2];

    float beta = clampb(braw);
    float lg = __logf(__fdividef(1.0f + beta, 1.0f - beta));
    float q = fmaf(0.25f * lg, lg, 0.1f);
    g_hit[i] = make_float4(ccv.x, ccv.y, q, __int_as_float(t));
    ccs += ccv.x * ccv.x + ccv.y * ccv.y;

    float ed = fabsf(tev - pev);
    float el = softclip_f(fmaf(10.0f, __expf(-0.1f * ed * ed), 0.01f * ed), 10.0f);
    float dx = tpv.x - ppv.x, dy = tpv.y - ppv.y;
    float pl = softclip_f(huber_f(sqrtf(fmaf(dx, dx, dy * dy) * 0.01f + 0.01f), 10.0f), 3.0f);
    float tl = softclip_f(huber_f(ttv - ptv, 2.0f), 6.0f);
    float s2 = pid0.x * pid0.x + pid0.y * pid0.y + pid1.x * pid1.x
             + pid1.y * pid1.y + pid2.x * pid2.x + pid2.y * pid2.y;
    float cl = 1e-8f * (s2 * (1.0f / 6.0f));
    float payload = el + pl + tl + cl;
    float w = tev > 10.0f ? 1.0f : fmaxf((tev - 0.5f) * (1.0f / 9.5f), 0.0f);
    float pw = beta * w;

    if (t >= 0) {
        atomicAdd(&g_cnt[t], 1);
        unsigned long long key =
            (((unsigned long long)__float_as_uint(beta)) << 32) |
            (unsigned long long)(0xFFFFFFFFu - (unsigned)i);
        atomicMax(&g_amax[t], key);
        asm volatile("red.global.add.v2.f32 [%0], {%1, %2};"
                     :: "l"(&g_numden[t]), "f"(payload * pw), "f"(pw) : "memory");
    } else {
        ns += beta; ncnt += 1.0f;
    }
}

// ---------------- kernel 1: per-hit pass + fused expanded-A-table build ------------
__global__ void __launch_bounds__(HTHR) k_hits(
        const float* __restrict__ pb,  const float* __restrict__ cc,
        const float* __restrict__ pe,  const float* __restrict__ pp,
        const float* __restrict__ pt,  const float* __restrict__ pid,
        const int*   __restrict__ tix, const float* __restrict__ te,
        const float* __restrict__ tp,  const float* __restrict__ tt) {
    __shared__ unsigned s_last;
    const int tid = blockIdx.x * HTHR + threadIdx.x;
    float ns = 0.0f, ncnt = 0.0f, ccs = 0.0f;
    process_hit(tid, pb, cc, pe, pp, pt, pid, tix, te, tp, tt, ns, ncnt, ccs);
    {   // extra chunk: every HWSTRIDE-th warp takes one 32-hit chunk
        int g = tid >> 5;
        int chunk = g / HWSTRIDE;
        if ((g % HWSTRIDE) == 0 && chunk < (HNEXTRA / 32)) {
            int i2 = HNT + chunk * 32 + (tid & 31);
            process_hit(i2, pb, cc, pe, pp, pt, pid, tix, te, tp, tt, ns, ncnt, ccs);
        }
    }

    #pragma unroll
    for (int o = 16; o > 0; o >>= 1) {
        ns   += __shfl_down_sync(0xFFFFFFFF, ns, o);
        ncnt += __shfl_down_sync(0xFFFFFFFF, ncnt, o);
        ccs  += __shfl_down_sync(0xFFFFFFFF, ccs, o);
    }
    if ((threadIdx.x & 31) == 0) {
        if (ns != 0.0f || ncnt != 0.0f) { atomicAdd(&g_noise_sum, ns); atomicAdd(&g_noise_cnt, ncnt); }
        atomicAdd(&g_cc_sum, ccs);
    }

    // ---- last block builds the expanded A-table ----
    __threadfence();
    if (threadIdx.x == 0) s_last = atomicAdd(&g_done_h, 1u);
    __syncthreads();
    if (s_last != gridDim.x - 1) return;

    #pragma unroll
    for (int kk = 0; kk < 2; kk++) {
        int k = threadIdx.x + kk * HTHR;
        int c = g_cnt[k];
        if (c > 0) {
            unsigned idx = 0xFFFFFFFFu - (unsigned)(g_amax[k] & 0xFFFFFFFFull);
            float b = clampb(pb[idx]);
            float lg = __logf(__fdividef(1.0f + b, 1.0f - b));
            float qa = fmaf(0.25f * lg, lg, 0.1f);
            float2 ccv = ((const float2*)cc)[idx];
            float fc = (float)c;
            g_A[k] = make_float4(-2.0f * ccv.x, -2.0f * ccv.y,
                                 fmaf(ccv.x, ccv.x, ccv.y * ccv.y) + 1e-6f,
                                 qa / ((float)NHIT - fc + EPSF));
            g_watt[k]   = qa / (fc + EPSF);
            g_beta_a[k] = b;
        } else {
            g_A[k] = make_float4(0.f, 0.f, 1e-6f, 0.f);   // wrep=0: inert
            g_watt[k] = 0.f; g_beta_a[k] = 1.f;
        }
    }
    if (threadIdx.x == 0) g_done_h = 0u;   // reset for next graph replay
}

// ---------------- member correction for one hit ----------------
__device__ __forceinline__ float member_corr(float4 h, float hx, float hy, float h2,
                                             const float4* sA) {
    int ti = __float_as_int(h.w);
    if (ti < 0) return 0.0f;
    float4 a = sA[ti];
    float v = fmaf(a.x, hx, a.z);
    v = fmaf(a.y, hy, v);
    float d2 = v + h2;
    float s = __saturatef(1.0f - sqapx(d2));
    return fmaf(-s, a.w, fmaf(d2 - 1e-6f, g_watt[ti], 0.0f));
}

// ---------------- kernel 2: 2 hits/thread, 1 block/SM, one LDS per 2 pairs --------
__global__ void __launch_bounds__(RTHR, 1) k_rep(float* __restrict__ out) {
    __shared__ float4 sA[KOBJ];          // 8KB
    __shared__ float s_red[2 * RTHR];
    __shared__ unsigned s_last;

    const int t = threadIdx.x;
    sA[t]        = g_A[t];
    sA[t + RTHR] = g_A[t + RTHR];
    __syncthreads();

    const int tid = blockIdx.x * RTHR + t;
    const int i0 = tid;
    const int i1 = tid + RNT;

    float4 h0 = g_hit[i0];
    float4 h1 = g_hit[i1];
    const float hx0 = h0.x, hy0 = h0.y, h20 = fmaf(hx0, hx0, hy0 * hy0);
    const float hx1 = h1.x, hy1 = h1.y, h21 = fmaf(hx1, hx1, hy1 * hy1);
    float acc0 = 0.0f, acc1 = 0.0f;

    #pragma unroll 8
    for (int k = 0; k < KOBJ; k++) {
        float4 a = sA[k];                 // one broadcast LDS.128 serves BOTH hits
        float v0 = fmaf(a.x, hx0, a.z);
        v0 = fmaf(a.y, hy0, v0);
        float d0 = v0 + h20;
        float s0 = __saturatef(1.0f - sqapx(d0));
        acc0 = fmaf(s0, a.w, acc0);

        float v1 = fmaf(a.x, hx1, a.z);
        v1 = fmaf(a.y, hy1, v1);
        float d1 = v1 + h21;
        float s1 = __saturatef(1.0f - sqapx(d1));
        acc1 = fmaf(s1, a.w, acc1);
    }
    acc0 += member_corr(h0, hx0, hy0, h20, sA);
    acc1 += member_corr(h1, hx1, hy1, h21, sA);
    float contrib = h0.z * acc0 + h1.z * acc1;

    // extra chunk: every RWSTRIDE-th warp takes one 32-hit chunk
    {
        int g = tid >> 5;
        int chunk = g / RWSTRIDE;
        if ((g % RWSTRIDE) == 0 && chunk < (RNEXTRA / 32)) {
            int i2 = RBASE + chunk * 32 + (tid & 31);
            float4 h = g_hit[i2];
            const float hx = h.x, hy = h.y, h2 = fmaf(hx, hx, hy * hy);
            float acc = 0.0f;
            #pragma unroll 8
            for (int k = 0; k < KOBJ; k++) {
                float4 a = sA[k];
                float v = fmaf(a.x, hx, a.z);
                v = fmaf(a.y, hy, v);
                float d2 = v + h2;
                float s = __saturatef(1.0f - sqapx(d2));
                acc = fmaf(s, a.w, acc);
            }
            acc += member_corr(h, hx, hy, h2, sA);
            contrib += h.z * acc;
        }
    }

    #pragma unroll
    for (int o = 16; o > 0; o >>= 1)
        contrib += __shfl_down_sync(0xFFFFFFFF, contrib, o);
    if ((t & 31) == 0) atomicAdd(&g_pairsum, contrib);

    // ---- last block finalizes + resets scratch for next graph replay ----
    __threadfence();
    if (t == 0) s_last = atomicAdd(&g_done_p, 1u);
    __syncthreads();
    if (s_last != gridDim.x - 1) return;

    float obj = 0.f, has = 0.f;
    #pragma unroll
    for (int kk = 0; kk < 2; kk++) {
        int k = t + kk * RTHR;
        int c = g_cnt[k];
        if (c > 0) {
            has += 1.0f;
            float2 nd = g_numden[k];
            obj += nd.x / (nd.y + EPSF) + (1.0f - g_beta_a[k]);
        }
        g_amax[k] = 0ull; g_cnt[k] = 0;
        g_numden[k] = make_float2(0.f, 0.f);
    }
    s_red[t] = obj; s_red[t + RTHR] = has;
    __syncthreads();
    #pragma unroll
    for (int o = RTHR / 2; o > 0; o >>= 1) {
        if (t < o) { s_red[t] += s_red[t + o]; s_red[t + RTHR] += s_red[t + RTHR + o]; }
        __syncthreads();
    }
    if (t == 0) {
        float n_obj = s_red[RTHR] + EPSF;
        float total = (s_red[0] + g_pairsum) / n_obj
                    + g_noise_sum / (g_noise_cnt + EPSF)
                    + 0.001f * g_cc_sum * (1.0f / (float)(NHIT * 2));
        out[0] = total;
        g_pairsum = 0.f; g_noise_sum = 0.f; g_noise_cnt = 0.f; g_cc_sum = 0.f;
        g_done_p = 0u;
    }
}

// ---------------- launch ----------------
extern "C" void kernel_launch(void* const* d_in, const int* in_sizes, int n_in,
                              void* d_out, int out_size) {
    const float* pb  = (const float*)d_in[0];
    const float* cc  = (const float*)d_in[1];
    const float* pe  = (const float*)d_in[2];
    const float* pp  = (const float*)d_in[3];
    const float* pt  = (const float*)d_in[4];
    const float* pid = (const float*)d_in[5];
    const int*   tix = (const int*)  d_in[6];
    const float* te  = (const float*)d_in[7];
    const float* tp  = (const float*)d_in[8];
    const float* tt  = (const float*)d_in[9];

    k_hits<<<HGRID, HTHR>>>(pb, cc, pe, pp, pt, pid, tix, te, tp, tt);
    k_rep<<<RGRID, RTHR>>>((float*)d_out);
}

// round 16
// speedup vs baseline: 1.3539x; 1.3539x over previous
#include <cuda_runtime.h>
#include <math.h>

#define NHIT 80000
#define KOBJ 512
#define GRID 313               // 313*256 = 80128 threads
#define THR  256
#define EPSF 1e-9f

// ---------------- scratch (device globals; zero at load, reset after use) ----------
__device__ float4 g_hit[NHIT];                 // x, y, q, t_idx (int bits)
__device__ float4 g_A[KOBJ];                   // -2ax, -2ay, |a|^2+1e-6, wrep
__device__ float  g_watt[KOBJ];                // q_a/(cnt+eps)
__device__ float  g_beta_a[KOBJ];
__device__ unsigned long long g_amax[KOBJ];    // packed (beta_bits<<32 | ~idx)
__device__ int    g_cnt[KOBJ];
__device__ float2 g_numden[KOBJ];              // payload num, den
__device__ float  g_pairsum, g_noise_sum, g_noise_cnt, g_cc_sum;
__device__ unsigned g_done_h, g_done_p;

__device__ __forceinline__ float clampb(float b) {
    return fminf(fmaxf(b, 1e-6f), 1.0f - 1e-6f);
}
__device__ __forceinline__ float softclip_f(float x, float c) {
    x = x * (1.0f / c);
    if (x > 1.0f) x = __logf(x + 1.0f);
    return x * c;
}
__device__ __forceinline__ float huber_f(float x, float d) {
    float ax = fabsf(x);
    return ax < d ? x * x : d * d + 2.0f * d * (ax - d);
}
__device__ __forceinline__ float sqapx(float x) {
    float s; asm("sqrt.approx.f32 %0, %1;" : "=f"(s) : "f"(x)); return s;
}

// ---------------- kernel 1: minimal per-hit pass + A-table build ----------------
// Loads ONLY pb, cc, tix (3 independent LDGs): latency-lean.
__global__ void __launch_bounds__(THR) k_pre(
        const float* __restrict__ pb, const float* __restrict__ cc,
        const int* __restrict__ tix) {
    __shared__ unsigned s_last;
    const int i = blockIdx.x * THR + threadIdx.x;
    float ns = 0.0f, ncnt = 0.0f, ccs = 0.0f;
    if (i < NHIT) {   // warp-uniform (80000 % 32 == 0)
        float  braw = pb[i];
        int    t    = tix[i];
        float2 ccv  = ((const float2*)cc)[i];

        float beta = clampb(braw);
        float lg = __logf(__fdividef(1.0f + beta, 1.0f - beta));
        float q = fmaf(0.25f * lg, lg, 0.1f);
        g_hit[i] = make_float4(ccv.x, ccv.y, q, __int_as_float(t));
        ccs = ccv.x * ccv.x + ccv.y * ccv.y;

        if (t >= 0) {
            atomicAdd(&g_cnt[t], 1);
            // argmax beta, ties -> lowest index (matches jnp.argmax)
            unsigned long long key =
                (((unsigned long long)__float_as_uint(beta)) << 32) |
                (unsigned long long)(0xFFFFFFFFu - (unsigned)i);
            atomicMax(&g_amax[t], key);
        } else {
            ns = beta; ncnt = 1.0f;
        }
    }
    #pragma unroll
    for (int o = 16; o > 0; o >>= 1) {
        ns   += __shfl_down_sync(0xFFFFFFFF, ns, o);
        ncnt += __shfl_down_sync(0xFFFFFFFF, ncnt, o);
        ccs  += __shfl_down_sync(0xFFFFFFFF, ccs, o);
    }
    if ((threadIdx.x & 31) == 0) {
        if (ns != 0.0f || ncnt != 0.0f) { atomicAdd(&g_noise_sum, ns); atomicAdd(&g_noise_cnt, ncnt); }
        atomicAdd(&g_cc_sum, ccs);
    }

    // ---- last block builds the expanded A-table ----
    __threadfence();
    if (threadIdx.x == 0) s_last = atomicAdd(&g_done_h, 1u);
    __syncthreads();
    if (s_last != gridDim.x - 1) return;

    #pragma unroll
    for (int kk = 0; kk < 2; kk++) {
        int k = threadIdx.x + kk * THR;
        int c = g_cnt[k];
        if (c > 0) {
            unsigned idx = 0xFFFFFFFFu - (unsigned)(g_amax[k] & 0xFFFFFFFFull);
            float b = clampb(pb[idx]);
            float lg = __logf(__fdividef(1.0f + b, 1.0f - b));
            float qa = fmaf(0.25f * lg, lg, 0.1f);
            float2 ccv = ((const float2*)cc)[idx];
            float fc = (float)c;
            g_A[k] = make_float4(-2.0f * ccv.x, -2.0f * ccv.y,
                                 fmaf(ccv.x, ccv.x, ccv.y * ccv.y) + 1e-6f,
                                 qa / ((float)NHIT - fc + EPSF));
            g_watt[k]   = qa / (fc + EPSF);
            g_beta_a[k] = b;
        } else {
            g_A[k] = make_float4(0.f, 0.f, 1e-6f, 0.f);   // wrep=0: inert
            g_watt[k] = 0.f; g_beta_a[k] = 1.f;
        }
    }
    if (threadIdx.x == 0) g_done_h = 0u;   // reset for next graph replay
}

// ---------------- kernel 2: payload + flattened N x K + finalize ----------------
__global__ void __launch_bounds__(THR, 4) k_rep(
        const float* __restrict__ pb,  const float* __restrict__ pe,
        const float* __restrict__ pp,  const float* __restrict__ pt,
        const float* __restrict__ pid, const float* __restrict__ te,
        const float* __restrict__ tp,  const float* __restrict__ tt,
        float* __restrict__ out) {
    __shared__ float4 sA[KOBJ];          // 8KB
    __shared__ float s_red[2 * THR];
    __shared__ unsigned s_last;

    const int t = threadIdx.x;
    const int i = blockIdx.x * THR + t;
    const bool valid = (i < NHIT);       // warp-uniform

    // ---- payload losses (LDGs issue first; latency hidden under staging/k-loop) ----
    float4 h = make_float4(0.f, 0.f, 0.f, __int_as_float(-1));
    if (valid) {
        h = g_hit[i];
        int ti = __float_as_int(h.w);
        if (ti >= 0) {
            float  braw = pb[i];
            float  pev  = pe[i];
            float2 ppv  = ((const float2*)pp)[i];
            float  ptv  = pt[i];
            float  tev  = te[i];
            float2 tpv  = ((const float2*)tp)[i];
            float  ttv  = tt[i];
            float2 pid0 = ((const float2*)pid)[3 * i];
            float2 pid1 = ((const float2*)pid)[3 * i + 1];
            float2 pid2 = ((const float2*)pid)[3 * i + 2];

            float beta = clampb(braw);
            float ed = fabsf(tev - pev);
            float el = softclip_f(fmaf(10.0f, __expf(-0.1f * ed * ed), 0.01f * ed), 10.0f);
            float dx = tpv.x - ppv.x, dy = tpv.y - ppv.y;
            float pl = softclip_f(huber_f(sqrtf(fmaf(dx, dx, dy * dy) * 0.01f + 0.01f), 10.0f), 3.0f);
            float tl = softclip_f(huber_f(ttv - ptv, 2.0f), 6.0f);
            float s2 = pid0.x * pid0.x + pid0.y * pid0.y + pid1.x * pid1.x
                     + pid1.y * pid1.y + pid2.x * pid2.x + pid2.y * pid2.y;
            float cl = 1e-8f * (s2 * (1.0f / 6.0f));
            float payload = el + pl + tl + cl;
            float w = tev > 10.0f ? 1.0f : fmaxf((tev - 0.5f) * (1.0f / 9.5f), 0.0f);
            float pw = beta * w;
            asm volatile("red.global.add.v2.f32 [%0], {%1, %2};"
                         :: "l"(&g_numden[ti]), "f"(payload * pw), "f"(pw) : "memory");
        }
    }

    // ---- stage A-table ----
    sA[t]       = g_A[t];
    sA[t + THR] = g_A[t + THR];
    __syncthreads();

    // ---- flattened N x K loop (R13's proven form) ----
    float contrib = 0.0f;
    if (valid) {
        const float hx = h.x, hy = h.y;
        const float h2 = fmaf(hx, hx, hy * hy);
        float acc = 0.0f;
        #pragma unroll 8
        for (int k = 0; k < KOBJ; k++) {
            float4 a = sA[k];            // uniform k -> broadcast LDS.128
            float v = fmaf(a.x, hx, a.z);      // -2ax*hx + |a|^2 + eps
            v = fmaf(a.y, hy, v);              // + -2ay*hy
            float d2 = v + h2;                 // = |h-a|^2 + eps
            float s = __saturatef(1.0f - sqapx(d2));
            acc = fmaf(s, a.w, acc);
        }
        // member terms: remove own-object repulsion (exact cancel), add attraction
        int ti = __float_as_int(h.w);
        if (ti >= 0) {
            float4 a = sA[ti];
            float v = fmaf(a.x, hx, a.z);
            v = fmaf(a.y, hy, v);
            float d2 = v + h2;
            float s = __saturatef(1.0f - sqapx(d2));
            acc = fmaf(-s, a.w, acc);
            acc = fmaf(d2 - 1e-6f, g_watt[ti], acc);
        }
        contrib = h.z * acc;
    }
    #pragma unroll
    for (int o = 16; o > 0; o >>= 1)
        contrib += __shfl_down_sync(0xFFFFFFFF, contrib, o);
    if ((t & 31) == 0) atomicAdd(&g_pairsum, contrib);

    // ---- last block finalizes + resets scratch for next graph replay ----
    __threadfence();
    if (t == 0) s_last = atomicAdd(&g_done_p, 1u);
    __syncthreads();
    if (s_last != gridDim.x - 1) return;

    float obj = 0.f, has = 0.f;
    #pragma unroll
    for (int kk = 0; kk < 2; kk++) {
        int k = t + kk * THR;
        int c = g_cnt[k];
        if (c > 0) {
            has += 1.0f;
            float2 nd = g_numden[k];
            obj += nd.x / (nd.y + EPSF) + (1.0f - g_beta_a[k]);
        }
        g_amax[k] = 0ull; g_cnt[k] = 0;
        g_numden[k] = make_float2(0.f, 0.f);
    }
    s_red[t] = obj; s_red[t + THR] = has;
    __syncthreads();
    #pragma unroll
    for (int o = THR / 2; o > 0; o >>= 1) {
        if (t < o) { s_red[t] += s_red[t + o]; s_red[t + THR] += s_red[t + THR + o]; }
        __syncthreads();
    }
    if (t == 0) {
        float n_obj = s_red[THR] + EPSF;
        float total = (s_red[0] + g_pairsum) / n_obj
                    + g_noise_sum / (g_noise_cnt + EPSF)
                    + 0.001f * g_cc_sum * (1.0f / (float)(NHIT * 2));
        out[0] = total;
        g_pairsum = 0.f; g_noise_sum = 0.f; g_noise_cnt = 0.f; g_cc_sum = 0.f;
        g_done_p = 0u;
    }
}

// ---------------- launch ----------------
extern "C" void kernel_launch(void* const* d_in, const int* in_sizes, int n_in,
                              void* d_out, int out_size) {
    const float* pb  = (const float*)d_in[0];
    const float* cc  = (const float*)d_in[1];
    const float* pe  = (const float*)d_in[2];
    const float* pp  = (const float*)d_in[3];
    const float* pt  = (const float*)d_in[4];
    const float* pid = (const float*)d_in[5];
    const int*   tix = (const int*)  d_in[6];
    const float* te  = (const float*)d_in[7];
    const float* tp  = (const float*)d_in[8];
    const float* tt  = (const float*)d_in[9];

    k_pre<<<GRID, THR>>>(pb, cc, tix);
    k_rep<<<GRID, THR>>>(pb, pe, pp, pt, pid, te, tp, tt, (float*)d_out);
}